// round 1
// baseline (speedup 1.0000x reference)
#include <cuda_runtime.h>
#include <math.h>

// ---------------- scratch ----------------
__device__ float g_bufA[800L*64*42*42];   // conv1 out
__device__ float g_bufB[800L*64*21*21];   // conv2 out
__device__ float g_bufC[800L*64*11*11];   // conv3 out
__device__ float g_bufD[800L*2304];       // conv4 out (embeddings)
__device__ float g_protos[8*5*2304];
__device__ float g_protoInv[8*5];

// ---------------- generic stride-2 3x3 conv + bias + relu ----------------
// Block: one image n, OYT output rows, all 64 couts.
// Shared: zero-padded input tile (CK cins x (2*OYT+1) rows x (2*OW+1) cols) + weight chunk.
// Thread: 8 couts x TPOS (strided) positions.
template<int CIN, int H, int OH, int PADLOW, int OYT, int TPOS, int CK, int PTHREADS>
__global__ void __launch_bounds__(PTHREADS*8)
conv_s2_kernel(const float* __restrict__ in, const float* __restrict__ wgt,
               const float* __restrict__ bias, float* __restrict__ out)
{
    constexpr int W = H, OW = OH;
    constexpr int RP = 2*OYT + 1;
    constexpr int WP = 2*OW + 1;
    constexpr int IN_SZ = CK*RP*WP;
    constexpr int W_SZ  = 64*CK*9;
    constexpr int NPOS  = OYT*OW;
    constexpr int NT    = PTHREADS*8;

    __shared__ float s_in[IN_SZ];
    __shared__ float s_w[W_SZ];

    const int n   = blockIdx.x;
    const int oy0 = blockIdx.y * OYT;
    const int tid = threadIdx.x;
    const int px  = tid % PTHREADS;
    const int cy  = tid / PTHREADS;     // cout group 0..7

    int  baseoff[TPOS], oyl_arr[TPOS], ox_arr[TPOS];
    bool valid[TPOS];
#pragma unroll
    for (int p = 0; p < TPOS; p++) {
        int pos = px + p*PTHREADS;               // strided -> adjacent lanes adjacent
        valid[p] = pos < NPOS;
        if (pos >= NPOS) pos = NPOS - 1;
        int oyl = pos / OW;
        int ox  = pos - oyl*OW;
        oyl_arr[p] = oyl; ox_arr[p] = ox;
        baseoff[p] = (2*oyl)*WP + 2*ox;
    }

    float acc[8][TPOS];
#pragma unroll
    for (int i = 0; i < 8; i++)
#pragma unroll
        for (int j = 0; j < TPOS; j++) acc[i][j] = 0.f;

    for (int c0 = 0; c0 < CIN; c0 += CK) {
        // stage zero-padded input tile
        for (int idx = tid; idx < IN_SZ; idx += NT) {
            int c   = idx / (RP*WP);
            int rem = idx - c*(RP*WP);
            int r   = rem / WP;
            int s   = rem - r*WP;
            int gr  = 2*oy0 + r - PADLOW;
            int gc  = s - PADLOW;
            float v = 0.f;
            if (gr >= 0 && gr < H && gc >= 0 && gc < W)
                v = in[((n*CIN + c0 + c)*H + gr)*W + gc];
            s_in[idx] = v;
        }
        // stage weight chunk: layout [cout][c][k]
        for (int idx = tid; idx < W_SZ; idx += NT) {
            int cout = idx / (CK*9);
            int rem  = idx - cout*(CK*9);
            s_w[idx] = wgt[(cout*CIN + c0)*9 + rem];
        }
        __syncthreads();

#pragma unroll
        for (int c = 0; c < CK; c++) {
            float xin[TPOS][9];
#pragma unroll
            for (int p = 0; p < TPOS; p++) {
                const float* bp = &s_in[c*(RP*WP) + baseoff[p]];
#pragma unroll
                for (int ky = 0; ky < 3; ky++)
#pragma unroll
                    for (int kx = 0; kx < 3; kx++)
                        xin[p][ky*3 + kx] = bp[ky*WP + kx];
            }
#pragma unroll
            for (int co = 0; co < 8; co++) {
                const float* wp = &s_w[((cy*8 + co)*CK + c)*9];
                float wl[9];
#pragma unroll
                for (int k = 0; k < 9; k++) wl[k] = wp[k];
#pragma unroll
                for (int p = 0; p < TPOS; p++) {
                    float a = acc[co][p];
#pragma unroll
                    for (int k = 0; k < 9; k++) a = fmaf(wl[k], xin[p][k], a);
                    acc[co][p] = a;
                }
            }
        }
        __syncthreads();
    }

    const int oy_valid = (OH - oy0 < OYT) ? (OH - oy0) : OYT;
#pragma unroll
    for (int co = 0; co < 8; co++) {
        const int cout = cy*8 + co;
        const float bb = bias[cout];
#pragma unroll
        for (int p = 0; p < TPOS; p++) {
            if (valid[p] && oyl_arr[p] < oy_valid) {
                float v = acc[co][p] + bb;
                out[((n*64 + cout)*OH + oy0 + oyl_arr[p])*OW + ox_arr[p]] = v > 0.f ? v : 0.f;
            }
        }
    }
}

// ---------------- prototypes + inverse norms ----------------
__global__ void protos_kernel(const float* __restrict__ emb, const int* __restrict__ y,
                              float* __restrict__ protos, float* __restrict__ protoInv)
{
    const int b = blockIdx.x / 5, c = blockIdx.x % 5;
    const int tid = threadIdx.x;                   // 256
    __shared__ int sels[25];
    if (tid < 25) sels[tid] = ((y[b*25 + tid] % 5) == c) ? 1 : 0;
    __syncthreads();

    float sq = 0.f;
    for (int d = tid; d < 2304; d += 256) {
        float v = 0.f;
#pragma unroll
        for (int s = 0; s < 25; s++)
            if (sels[s]) v += emb[(b*25 + s)*2304 + d];
        v = v / 5.0f;                              // CAP = 5
        protos[(b*5 + c)*2304 + d] = v;
        sq += v*v;
    }
    __shared__ float red[256];
    red[tid] = sq; __syncthreads();
    for (int s = 128; s > 0; s >>= 1) {
        if (tid < s) red[tid] += red[tid + s];
        __syncthreads();
    }
    if (tid == 0) protoInv[b*5 + c] = 1.f / fmaxf(sqrtf(red[0]), 1e-8f);
}

// ---------------- cosine logits ----------------
__global__ void preds_kernel(const float* __restrict__ emb, const float* __restrict__ protos,
                             const float* __restrict__ protoInv, float* __restrict__ out)
{
    const int b = blockIdx.x / 75, t = blockIdx.x % 75;
    const int tid = threadIdx.x;                   // 256
    float dot[5] = {0,0,0,0,0};
    float nsq = 0.f;
    const float* e = emb + (size_t)(200 + b*75 + t)*2304;
    for (int d = tid; d < 2304; d += 256) {
        float ev = e[d];
        nsq += ev*ev;
#pragma unroll
        for (int c = 0; c < 5; c++)
            dot[c] = fmaf(ev, protos[(b*5 + c)*2304 + d], dot[c]);
    }
    __shared__ float red[256];
    __shared__ float res[6];
    for (int q = 0; q < 6; q++) {
        red[tid] = (q == 0) ? nsq : dot[q-1];
        __syncthreads();
        for (int s = 128; s > 0; s >>= 1) {
            if (tid < s) red[tid] += red[tid + s];
            __syncthreads();
        }
        if (tid == 0) res[q] = red[0];
        __syncthreads();
    }
    if (tid < 5) {
        float inv_t = 1.f / fmaxf(sqrtf(res[0]), 1e-8f);
        out[(b*75 + t)*5 + tid] = res[1 + tid] * inv_t * protoInv[b*5 + tid];
    }
}

// ---------------- launch ----------------
extern "C" void kernel_launch(void* const* d_in, const int* in_sizes, int n_in,
                              void* d_out, int out_size)
{
    const float* xs = (const float*)d_in[0];
    const float* xt = (const float*)d_in[1];
    const int*   y  = (const int*)  d_in[2];
    const float* W1 = (const float*)d_in[3];
    const float* b1 = (const float*)d_in[4];
    const float* W2 = (const float*)d_in[5];
    const float* b2 = (const float*)d_in[6];
    const float* W3 = (const float*)d_in[7];
    const float* b3 = (const float*)d_in[8];
    const float* W4 = (const float*)d_in[9];
    const float* b4 = (const float*)d_in[10];
    float* out = (float*)d_out;

    float *bufA, *bufB, *bufC, *bufD, *pr, *pi;
    cudaGetSymbolAddress((void**)&bufA, g_bufA);
    cudaGetSymbolAddress((void**)&bufB, g_bufB);
    cudaGetSymbolAddress((void**)&bufC, g_bufC);
    cudaGetSymbolAddress((void**)&bufD, g_bufD);
    cudaGetSymbolAddress((void**)&pr,   g_protos);
    cudaGetSymbolAddress((void**)&pi,   g_protoInv);

    // conv1: 3->64, 84->42, pad_low=0  (support then target into one buffer)
    conv_s2_kernel<3,84,42,0, 3,4,3, 32><<<dim3(200,14), 256>>>(xs, W1, b1, bufA);
    conv_s2_kernel<3,84,42,0, 3,4,3, 32><<<dim3(600,14), 256>>>(xt, W1, b1, bufA + (size_t)200*64*42*42);
    // conv2: 64->64, 42->21, pad_low=0
    conv_s2_kernel<64,42,21,0, 6,4,8, 32><<<dim3(800,4), 256>>>(bufA, W2, b2, bufB);
    // conv3: 64->64, 21->11, pad_low=1
    conv_s2_kernel<64,21,11,1, 11,4,8, 31><<<dim3(800,1), 248>>>(bufB, W3, b3, bufC);
    // conv4: 64->64, 11->6, pad_low=1
    conv_s2_kernel<64,11,6,1, 6,2,8, 18><<<dim3(800,1), 144>>>(bufC, W4, b4, bufD);
    // head
    protos_kernel<<<40, 256>>>(bufD, y, pr, pi);
    preds_kernel<<<600, 256>>>(bufD, pr, pi, out);
}